// round 5
// baseline (speedup 1.0000x reference)
#include <cuda_runtime.h>
#include <cuda_bf16.h>
#include <cstdint>
#include <cstddef>

#define BB   256
#define LL   512
#define EE   256
#define HH   128
#define G4   512
#define TB   8
#define MROWS 131072          // L*B rows per cell
#define KTOT  768             // 3 * 256 (hi|hi|lo split-K)
#define NCH   24              // 768 / 32

// ---------------------------------------------------------------------------
// Device scratch
// ---------------------------------------------------------------------------
__device__ float g_gx[(size_t)2 * LL * BB * G4];            // 512 MB gates
__device__ __nv_bfloat16 g_ap[(size_t)2 * MROWS * KTOT];    // 402 MB A' (hi|hi|lo)
__device__ __nv_bfloat16 g_wp[(size_t)2 * G4 * KTOT];       // 1.5 MB W' (hi|lo|hi)
__device__ float g_h[(size_t)2 * BB * LL * HH];             // 128 MB hidden states

// ---------------------------------------------------------------------------
// Helpers
// ---------------------------------------------------------------------------
static __device__ __forceinline__ unsigned long long pack2(float x, float y) {
    unsigned long long r;
    asm("mov.b64 %0, {%1, %2};" : "=l"(r) : "f"(x), "f"(y));
    return r;
}
static __device__ __forceinline__ void fma2(unsigned long long& d,
                                            unsigned long long a,
                                            unsigned long long b) {
    asm("fma.rn.f32x2 %0, %1, %2, %0;" : "+l"(d) : "l"(a), "l"(b));
}
static __device__ __forceinline__ float2 unpack2(unsigned long long v) {
    float2 f;
    asm("mov.b64 {%0, %1}, %2;" : "=f"(f.x), "=f"(f.y) : "l"(v));
    return f;
}
static __device__ __forceinline__ uint32_t smem_u32(const void* p) {
    uint32_t a;
    asm("{ .reg .u64 t; cvta.to.shared.u64 t, %1; cvt.u32.u64 %0, t; }"
        : "=r"(a) : "l"(p));
    return a;
}
static __device__ __forceinline__ void st_remote_f32(uint32_t laddr, uint32_t peer, float v) {
    asm volatile(
        "{ .reg .b32 ra; mapa.shared::cluster.u32 ra, %0, %1; "
        "st.shared::cluster.f32 [ra], %2; }"
        :: "r"(laddr), "r"(peer), "f"(v) : "memory");
}
// fast activations (ex2/rcp approx)
static __device__ __forceinline__ float sigm(float x) {
    float t;
    asm("mul.f32 %0, %1, 0fBFB8AA3B;" : "=f"(t) : "f"(x));   // -x*log2(e)
    asm("ex2.approx.f32 %0, %0;" : "+f"(t));
    float r = t + 1.0f;
    asm("rcp.approx.f32 %0, %0;" : "+f"(r));
    return r;
}
static __device__ __forceinline__ float tanha(float x) {
    x = fminf(fmaxf(x, -9.0f), 9.0f);
    float t;
    asm("mul.f32 %0, %1, 0f4038AA3B;" : "=f"(t) : "f"(x));   // 2x*log2(e)
    asm("ex2.approx.f32 %0, %0;" : "+f"(t));                  // e^{2x}
    float den = t + 1.0f;
    asm("rcp.approx.f32 %0, %0;" : "+f"(den));
    return (t - 1.0f) * den;
}
// cp.async
static __device__ __forceinline__ void cp16(uint32_t dst, const void* src) {
    asm volatile("cp.async.cg.shared.global [%0], [%1], 16;"
                 :: "r"(dst), "l"(src) : "memory");
}
static __device__ __forceinline__ void cp_commit() {
    asm volatile("cp.async.commit_group;" ::: "memory");
}
template <int N>
static __device__ __forceinline__ void cp_wait() {
    asm volatile("cp.async.wait_group %0;" :: "n"(N) : "memory");
}
// ldmatrix x4 (b16)
static __device__ __forceinline__ void ldx4(uint32_t* r, uint32_t addr) {
    asm volatile("ldmatrix.sync.aligned.m8n8.x4.shared.b16 {%0,%1,%2,%3}, [%4];"
                 : "=r"(r[0]), "=r"(r[1]), "=r"(r[2]), "=r"(r[3]) : "r"(addr));
}
// bf16 HMMA m16n8k16, fp32 accum
static __device__ __forceinline__ void mma16816(float* c, const uint32_t* a,
                                                uint32_t b0, uint32_t b1) {
    asm volatile(
        "mma.sync.aligned.m16n8k16.row.col.f32.bf16.bf16.f32 "
        "{%0,%1,%2,%3}, {%4,%5,%6,%7}, {%8,%9}, {%0,%1,%2,%3};"
        : "+f"(c[0]), "+f"(c[1]), "+f"(c[2]), "+f"(c[3])
        : "r"(a[0]), "r"(a[1]), "r"(a[2]), "r"(a[3]), "r"(b0), "r"(b1));
}
static __device__ __forceinline__ uint32_t bfpack(__nv_bfloat16 a, __nv_bfloat16 b) {
    return (uint32_t)__bfloat16_as_ushort(a) | ((uint32_t)__bfloat16_as_ushort(b) << 16);
}

// ---------------------------------------------------------------------------
// Convert X -> A' = [hi | hi | lo]  (bf16, row r = t*256+b, K'=768)
// ---------------------------------------------------------------------------
__global__ __launch_bounds__(256) void k_convert(const float* __restrict__ Xh,
                                                 const float* __restrict__ Xf) {
    size_t i = (size_t)blockIdx.x * 256 + threadIdx.x;
    int e8 = (int)(i & 31);
    size_t rr = i >> 5;                                  // cell*MROWS + r
    int cell = (int)(rr >> 17);
    int r = (int)(rr & (MROWS - 1));
    int t = r >> 8, b = r & 255;
    const float* X = cell ? Xf : Xh;
    const float4* src = reinterpret_cast<const float4*>(X + ((size_t)b * LL + t) * EE + e8 * 8);
    float4 v0 = src[0], v1 = src[1];
    float x[8] = {v0.x, v0.y, v0.z, v0.w, v1.x, v1.y, v1.z, v1.w};
    __nv_bfloat16 hi[8], lo[8];
#pragma unroll
    for (int j = 0; j < 8; j++) {
        hi[j] = __float2bfloat16(x[j]);
        lo[j] = __float2bfloat16(x[j] - __bfloat162float(hi[j]));
    }
    uint4 ph, pl;
    ph.x = bfpack(hi[0], hi[1]); ph.y = bfpack(hi[2], hi[3]);
    ph.z = bfpack(hi[4], hi[5]); ph.w = bfpack(hi[6], hi[7]);
    pl.x = bfpack(lo[0], lo[1]); pl.y = bfpack(lo[2], lo[3]);
    pl.z = bfpack(lo[4], lo[5]); pl.w = bfpack(lo[6], lo[7]);
    __nv_bfloat16* dst = g_ap + rr * KTOT + e8 * 8;
    *reinterpret_cast<uint4*>(dst)       = ph;
    *reinterpret_cast<uint4*>(dst + 256) = ph;
    *reinterpret_cast<uint4*>(dst + 512) = pl;
}

// W' = [hi | lo | hi]
__global__ __launch_bounds__(256) void k_convert_w(const float* __restrict__ Wh,
                                                   const float* __restrict__ Wf) {
    int i = blockIdx.x * 256 + threadIdx.x;
    int e8 = i & 31;
    int nn = i >> 5;                                     // cell*512 + n
    int cell = nn >> 9;
    int n = nn & 511;
    const float* W = cell ? Wf : Wh;
    const float4* src = reinterpret_cast<const float4*>(W + (size_t)n * EE + e8 * 8);
    float4 v0 = src[0], v1 = src[1];
    float x[8] = {v0.x, v0.y, v0.z, v0.w, v1.x, v1.y, v1.z, v1.w};
    __nv_bfloat16 hi[8], lo[8];
#pragma unroll
    for (int j = 0; j < 8; j++) {
        hi[j] = __float2bfloat16(x[j]);
        lo[j] = __float2bfloat16(x[j] - __bfloat162float(hi[j]));
    }
    uint4 ph, pl;
    ph.x = bfpack(hi[0], hi[1]); ph.y = bfpack(hi[2], hi[3]);
    ph.z = bfpack(hi[4], hi[5]); ph.w = bfpack(hi[6], hi[7]);
    pl.x = bfpack(lo[0], lo[1]); pl.y = bfpack(lo[2], lo[3]);
    pl.z = bfpack(lo[4], lo[5]); pl.w = bfpack(lo[6], lo[7]);
    __nv_bfloat16* dst = g_wp + (size_t)nn * KTOT + e8 * 8;
    *reinterpret_cast<uint4*>(dst)       = ph;
    *reinterpret_cast<uint4*>(dst + 256) = pl;   // pairs with A hi
    *reinterpret_cast<uint4*>(dst + 512) = ph;   // pairs with A lo
}

// ---------------------------------------------------------------------------
// Phase 1 GEMM via mma.sync bf16 (unchanged from R4 — validated)
// ---------------------------------------------------------------------------
#define ASTRIDE 40

__global__ __launch_bounds__(256, 2) void k_mma_gemm(
    const float* __restrict__ bih_h, const float* __restrict__ bhh_h,
    const float* __restrict__ bih_f, const float* __restrict__ bhh_f)
{
    __shared__ __align__(16) __nv_bfloat16 As[2][128 * ASTRIDE];
    __shared__ __align__(16) __nv_bfloat16 Bs[2][128 * ASTRIDE];
    __shared__ float bias_s[128];

    const int tid  = threadIdx.x;
    const int wid  = tid >> 5;
    const int lane = tid & 31;
    const int n0 = blockIdx.x * 128;
    const int m0 = blockIdx.y * 128;
    const int cell = m0 >> 17;

    if (tid < 128) {
        const float* bi = cell ? bih_f : bih_h;
        const float* bh = cell ? bhh_f : bhh_h;
        bias_s[tid] = bi[n0 + tid] + bh[n0 + tid];
    }

    const __nv_bfloat16* Asrc = g_ap + (size_t)m0 * KTOT;
    const __nv_bfloat16* Bsrc = g_wp + ((size_t)cell * G4 + n0) * KTOT;

    const uint32_t sa = smem_u32(&As[0][0]);
    const uint32_t sb = smem_u32(&Bs[0][0]);
    const uint32_t bufstride = 128 * ASTRIDE * 2;

    const int lrow = tid >> 1;
    const int lu   = (tid & 1) * 2;
    const uint32_t a_dst0 = sa + lrow * (ASTRIDE * 2) + lu * 16;
    const uint32_t b_dst0 = sb + lrow * (ASTRIDE * 2) + lu * 16;
    const __nv_bfloat16* a_src0 = Asrc + (size_t)lrow * KTOT + lu * 8;
    const __nv_bfloat16* b_src0 = Bsrc + (size_t)lrow * KTOT + lu * 8;

#define LOAD_CHUNK(c)                                                      \
    do {                                                                   \
        int _buf = (c) & 1;                                                \
        int _k0 = (c) * 32;                                                \
        cp16(a_dst0 + _buf * bufstride,      a_src0 + _k0);                \
        cp16(a_dst0 + _buf * bufstride + 16, a_src0 + _k0 + 8);            \
        cp16(b_dst0 + _buf * bufstride,      b_src0 + _k0);                \
        cp16(b_dst0 + _buf * bufstride + 16, b_src0 + _k0 + 8);            \
        cp_commit();                                                       \
    } while (0)

    const int warp_m = wid & 3;
    const int warp_n = wid >> 2;

    uint32_t a_addr[2];
#pragma unroll
    for (int im = 0; im < 2; im++) {
        int row = warp_m * 32 + im * 16 + (lane & 15);
        a_addr[im] = sa + row * (ASTRIDE * 2) + (lane >> 4) * 16;
    }
    uint32_t b_addr[4];
#pragma unroll
    for (int ip = 0; ip < 4; ip++) {
        int row = warp_n * 64 + ip * 16 + (lane >> 4) * 8 + (lane & 7);
        b_addr[ip] = sb + row * (ASTRIDE * 2) + ((lane >> 3) & 1) * 16;
    }

    float acc[2][8][4];
#pragma unroll
    for (int im = 0; im < 2; im++)
#pragma unroll
        for (int in = 0; in < 8; in++)
#pragma unroll
            for (int q = 0; q < 4; q++) acc[im][in][q] = 0.0f;

    LOAD_CHUNK(0);

    for (int c = 0; c < NCH; ++c) {
        if (c + 1 < NCH) { LOAD_CHUNK(c + 1); cp_wait<1>(); }
        else             { cp_wait<0>(); }
        __syncthreads();

        const uint32_t boff = (uint32_t)(c & 1) * bufstride;
#pragma unroll
        for (int ks = 0; ks < 2; ks++) {
            const uint32_t kb = boff + ks * 32;
            uint32_t afr[2][4];
            ldx4(afr[0], a_addr[0] + kb);
            ldx4(afr[1], a_addr[1] + kb);
            uint32_t bfr[16];
            ldx4(bfr + 0,  b_addr[0] + kb);
            ldx4(bfr + 4,  b_addr[1] + kb);
            ldx4(bfr + 8,  b_addr[2] + kb);
            ldx4(bfr + 12, b_addr[3] + kb);
#pragma unroll
            for (int im = 0; im < 2; im++)
#pragma unroll
                for (int in = 0; in < 8; in++)
                    mma16816(acc[im][in], afr[im], bfr[in * 2], bfr[in * 2 + 1]);
        }
        __syncthreads();
    }

#pragma unroll
    for (int im = 0; im < 2; im++) {
#pragma unroll
        for (int h = 0; h < 2; h++) {
            int m = m0 + warp_m * 32 + im * 16 + h * 8 + (lane >> 2);
            int r = m & (MROWS - 1);
            int t = r >> 8, b = r & 255;
            float* gp = g_gx + (((size_t)cell * LL + t) * BB + b) * G4 + n0;
#pragma unroll
            for (int in = 0; in < 8; in++) {
                int col = warp_n * 64 + in * 8 + (lane & 3) * 2;
                float2 v;
                v.x = acc[im][in][2 * h + 0] + bias_s[col];
                v.y = acc[im][in][2 * h + 1] + bias_s[col + 1];
                *reinterpret_cast<float2*>(gp + col) = v;
            }
        }
    }
}

// ---------------------------------------------------------------------------
// Phase 2: recurrent LSTM. Cluster of 2 CTAs per chain, 512 threads/CTA.
// Matvec: thread (row = tid>>1, half = tid&1) owns half a gate row in regs;
// partner combine via shfl.xor(1). Pointwise: thread (b = tid>>6, j = tid&63)
// owns one (batch, hidden-unit); c in a register; h stored to smem (local +
// remote via mapa) and to g_h for deferred FFN. One __syncthreads + one
// cluster barrier per step.
// ---------------------------------------------------------------------------
#define HPAD 136                         // 128 + 8 (swizzle pad)
static __device__ __forceinline__ int hidx(int j) { return j + ((j >> 6) << 2); }

__global__ __launch_bounds__(512, 1) __cluster_dims__(2, 1, 1)
void k_recurrent(const float* __restrict__ Whh_h,
                 const float* __restrict__ Whh_f)
{
    __shared__ float h_s[2][TB][HPAD];      // 8.7 KB double-buffered hidden
    __shared__ float gates_s[256][TB + 1];  // 9.2 KB h.W partials

    const int tid = threadIdx.x;
    uint32_t rank;
    asm("mov.u32 %0, %%cluster_ctarank;" : "=r"(rank));
    const int q    = blockIdx.x >> 1;
    const int cell = q >> 5;
    const int b0   = (q & 31) * TB;

    const float* W = cell ? Whh_f : Whh_h;

    // matvec mapping
    const int row  = tid >> 1;              // 0..255 local gate row
    const int half = tid & 1;
    const int g    = row >> 6;
    const int jj   = row & 63;
    const int n    = g * HH + (int)rank * 64 + jj;   // global gate row

    // half-row weights in registers: 64 floats = 32 f32x2
    unsigned long long w2[32];
    {
        const float2* wrow = reinterpret_cast<const float2*>(W + (size_t)n * HH + half * 64);
#pragma unroll
        for (int i = 0; i < 32; i++) {
            float2 v = wrow[i];
            w2[i] = pack2(v.x, v.y);
        }
    }

    // pointwise mapping
    const int pb = tid >> 6;                // 0..7
    const int pj = tid & 63;
    const int jglob = (int)rank * 64 + pj;
    const uint32_t h_local0 = smem_u32(&h_s[0][pb][hidx(jglob)]);
    const uint32_t h_local1 = smem_u32(&h_s[1][pb][hidx(jglob)]);
    float* hg = g_h + (((size_t)cell * BB + b0 + pb) * LL) * HH + jglob;

    // zero-init
    for (int i = tid; i < 2 * TB * HPAD; i += 512) (&h_s[0][0][0])[i] = 0.0f;
    float c_reg = 0.0f;
    __syncthreads();
    asm volatile("barrier.cluster.arrive.aligned;" ::: "memory");
    asm volatile("barrier.cluster.wait.aligned;"   ::: "memory");

    // Gx addressing (pointwise threads): 4 gate rows for (pj), batch pb.
    // addr(t, gi) = g_gx + ((cell*LL + t)*BB + b0+pb)*G4 + gi*128 + rank*64 + pj
    const float* gxbase = g_gx + ((size_t)cell * LL * BB + (b0 + pb)) * G4
                               + (size_t)rank * 64 + pj;
    float gxr[4];
#pragma unroll
    for (int gi = 0; gi < 4; gi++)
        gxr[gi] = gxbase[gi * HH];          // t = 0

    int buf = 0;
    for (int t = 0; t < LL; t++) {
        // ---- matvec: gates_s[row][b] = h[b] . w_half (both halves combined)
#pragma unroll
        for (int bp = 0; bp < TB; bp += 2) {
            const longlong2* hp0 =
                reinterpret_cast<const longlong2*>(&h_s[buf][bp][half * 68]);
            const longlong2* hp1 =
                reinterpret_cast<const longlong2*>(&h_s[buf][bp + 1][half * 68]);
            unsigned long long a00 = 0ull, a01 = 0ull, a10 = 0ull, a11 = 0ull;
#pragma unroll
            for (int i = 0; i < 16; i++) {
                longlong2 v0 = hp0[i];
                longlong2 v1 = hp1[i];
                fma2(a00, (unsigned long long)v0.x, w2[2 * i]);
                fma2(a01, (unsigned long long)v0.y, w2[2 * i + 1]);
                fma2(a10, (unsigned long long)v1.x, w2[2 * i]);
                fma2(a11, (unsigned long long)v1.y, w2[2 * i + 1]);
            }
            float2 s00 = unpack2(a00), s01 = unpack2(a01);
            float2 s10 = unpack2(a10), s11 = unpack2(a11);
            float p0 = (s00.x + s00.y) + (s01.x + s01.y);
            float p1 = (s10.x + s10.y) + (s11.x + s11.y);
            float t0 = p0 + __shfl_xor_sync(0xffffffffu, p0, 1);
            float t1 = p1 + __shfl_xor_sync(0xffffffffu, p1, 1);
            if (!half) {
                gates_s[row][bp]     = t0;
                gates_s[row][bp + 1] = t1;
            }
        }
        __syncthreads();

        // ---- pointwise (all 512 threads, unit = (pb, pj))
        float gi_ = gates_s[pj][pb]        + gxr[0];
        float gf_ = gates_s[64 + pj][pb]   + gxr[1];
        float gg_ = gates_s[128 + pj][pb]  + gxr[2];
        float go_ = gates_s[192 + pj][pb]  + gxr[3];
        float ig = sigm(gi_);
        float fg = sigm(gf_);
        float gv = tanha(gg_);
        float og = sigm(go_);
        c_reg = fg * c_reg + ig * gv;
        float hv = og * tanha(c_reg);

        const int nb = buf ^ 1;
        h_s[nb][pb][hidx(jglob)] = hv;
        st_remote_f32(nb ? h_local1 : h_local0, rank ^ 1u, hv);
        hg[(size_t)t * HH] = hv;

        // prefetch Gx for t+1 (hidden under next step's matvec)
        if (t + 1 < LL) {
            const float* gp = gxbase + (size_t)(t + 1) * BB * G4;
#pragma unroll
            for (int gi2 = 0; gi2 < 4; gi2++)
                gxr[gi2] = gp[gi2 * HH];
        }

        asm volatile("barrier.cluster.arrive.aligned;" ::: "memory");
        asm volatile("barrier.cluster.wait.aligned;"   ::: "memory");
        buf = nb;
    }
}

// ---------------------------------------------------------------------------
// Phase 3: y[b][t] = W_ffn . [h_h(b,t); h_f(b,t)] + b_ffn
// one block per b; thread handles t, t+256; rows are L1-resident on reuse.
// ---------------------------------------------------------------------------
__global__ __launch_bounds__(256) void k_finalize(float* __restrict__ out,
                                                  const float* __restrict__ Wffn,
                                                  const float* __restrict__ bffn) {
    __shared__ float wf[2 * HH];
    const int b = blockIdx.x;
    const int tid = threadIdx.x;
    wf[tid] = Wffn[tid];
    __syncthreads();
    const float bias = bffn[0];

    for (int t = tid; t < LL; t += 256) {
        const float4* p0 = reinterpret_cast<const float4*>(
            g_h + (((size_t)0 * BB + b) * LL + t) * HH);
        const float4* p1 = reinterpret_cast<const float4*>(
            g_h + (((size_t)1 * BB + b) * LL + t) * HH);
        float acc = bias;
#pragma unroll 8
        for (int q = 0; q < 32; q++) {
            float4 a = p0[q];
            acc += a.x * wf[4 * q] + a.y * wf[4 * q + 1]
                 + a.z * wf[4 * q + 2] + a.w * wf[4 * q + 3];
        }
#pragma unroll 8
        for (int q = 0; q < 32; q++) {
            float4 a = p1[q];
            acc += a.x * wf[128 + 4 * q] + a.y * wf[128 + 4 * q + 1]
                 + a.z * wf[128 + 4 * q + 2] + a.w * wf[128 + 4 * q + 3];
        }
        out[(size_t)b * LL + t] = acc;
    }
}

// ---------------------------------------------------------------------------
extern "C" void kernel_launch(void* const* d_in, const int* in_sizes, int n_in,
                              void* d_out, int out_size) {
    const float* hist  = (const float*)d_in[0];
    const float* fut   = (const float*)d_in[1];
    const float* Wih_h = (const float*)d_in[2];
    const float* Whh_h = (const float*)d_in[3];
    const float* bih_h = (const float*)d_in[4];
    const float* bhh_h = (const float*)d_in[5];
    const float* Wih_f = (const float*)d_in[6];
    const float* Whh_f = (const float*)d_in[7];
    const float* bih_f = (const float*)d_in[8];
    const float* bhh_f = (const float*)d_in[9];
    const float* Wffn  = (const float*)d_in[10];
    const float* bffn  = (const float*)d_in[11];
    float* out = (float*)d_out;

    k_convert<<<(2 * MROWS * 32) / 256, 256>>>(hist, fut);
    k_convert_w<<<(2 * G4 * 32) / 256, 256>>>(Wih_h, Wih_f);

    dim3 gg(G4 / 128, (2 * MROWS) / 128);   // (4, 2048)
    k_mma_gemm<<<gg, 256>>>(bih_h, bhh_h, bih_f, bhh_f);

    k_recurrent<<<128, 512>>>(Whh_h, Whh_f);

    k_finalize<<<BB, 256>>>(out, Wffn, bffn);
}

// round 6
// speedup vs baseline: 1.0646x; 1.0646x over previous
#include <cuda_runtime.h>
#include <cuda_bf16.h>
#include <cstdint>
#include <cstddef>

#define BB   256
#define LL   512
#define EE   256
#define HH   128
#define G4   512
#define TB   8
#define MROWS 131072          // L*B rows per cell
#define KTOT  768             // 3 * 256 (hi|hi|lo split-K)
#define NCH   24              // 768 / 32

// ---------------------------------------------------------------------------
// Device scratch
// ---------------------------------------------------------------------------
__device__ float g_gx[(size_t)2 * LL * BB * G4];            // 512 MB gates
__device__ __nv_bfloat16 g_ap[(size_t)2 * MROWS * KTOT];    // 402 MB A' (hi|hi|lo)
__device__ __nv_bfloat16 g_wp[(size_t)2 * G4 * KTOT];       // 1.5 MB W' (hi|lo|hi)
__device__ float g_h[(size_t)2 * BB * LL * HH];             // 128 MB hidden states

// ---------------------------------------------------------------------------
// Helpers
// ---------------------------------------------------------------------------
static __device__ __forceinline__ unsigned long long pack2(float x, float y) {
    unsigned long long r;
    asm("mov.b64 %0, {%1, %2};" : "=l"(r) : "f"(x), "f"(y));
    return r;
}
static __device__ __forceinline__ void fma2(unsigned long long& d,
                                            unsigned long long a,
                                            unsigned long long b) {
    asm("fma.rn.f32x2 %0, %1, %2, %0;" : "+l"(d) : "l"(a), "l"(b));
}
static __device__ __forceinline__ float2 unpack2(unsigned long long v) {
    float2 f;
    asm("mov.b64 {%0, %1}, %2;" : "=f"(f.x), "=f"(f.y) : "l"(v));
    return f;
}
static __device__ __forceinline__ uint32_t smem_u32(const void* p) {
    uint32_t a;
    asm("{ .reg .u64 t; cvta.to.shared.u64 t, %1; cvt.u32.u64 %0, t; }"
        : "=r"(a) : "l"(p));
    return a;
}
static __device__ __forceinline__ void st_remote_f32(uint32_t laddr, uint32_t peer, float v) {
    asm volatile(
        "{ .reg .b32 ra; mapa.shared::cluster.u32 ra, %0, %1; "
        "st.shared::cluster.f32 [ra], %2; }"
        :: "r"(laddr), "r"(peer), "f"(v) : "memory");
}
// fast activations (ex2/rcp approx)
static __device__ __forceinline__ float sigm(float x) {
    float t;
    asm("mul.f32 %0, %1, 0fBFB8AA3B;" : "=f"(t) : "f"(x));   // -x*log2(e)
    asm("ex2.approx.f32 %0, %0;" : "+f"(t));
    float r = t + 1.0f;
    asm("rcp.approx.f32 %0, %0;" : "+f"(r));
    return r;
}
static __device__ __forceinline__ float tanha(float x) {
    x = fminf(fmaxf(x, -9.0f), 9.0f);
    float t;
    asm("mul.f32 %0, %1, 0f4038AA3B;" : "=f"(t) : "f"(x));   // 2x*log2(e)
    asm("ex2.approx.f32 %0, %0;" : "+f"(t));                  // e^{2x}
    float den = t + 1.0f;
    asm("rcp.approx.f32 %0, %0;" : "+f"(den));
    return (t - 1.0f) * den;
}
// cp.async
static __device__ __forceinline__ void cp16(uint32_t dst, const void* src) {
    asm volatile("cp.async.cg.shared.global [%0], [%1], 16;"
                 :: "r"(dst), "l"(src) : "memory");
}
static __device__ __forceinline__ void cp_commit() {
    asm volatile("cp.async.commit_group;" ::: "memory");
}
template <int N>
static __device__ __forceinline__ void cp_wait() {
    asm volatile("cp.async.wait_group %0;" :: "n"(N) : "memory");
}
// ldmatrix x4 (b16)
static __device__ __forceinline__ void ldx4(uint32_t* r, uint32_t addr) {
    asm volatile("ldmatrix.sync.aligned.m8n8.x4.shared.b16 {%0,%1,%2,%3}, [%4];"
                 : "=r"(r[0]), "=r"(r[1]), "=r"(r[2]), "=r"(r[3]) : "r"(addr));
}
// bf16 HMMA m16n8k16, fp32 accum
static __device__ __forceinline__ void mma16816(float* c, const uint32_t* a,
                                                uint32_t b0, uint32_t b1) {
    asm volatile(
        "mma.sync.aligned.m16n8k16.row.col.f32.bf16.bf16.f32 "
        "{%0,%1,%2,%3}, {%4,%5,%6,%7}, {%8,%9}, {%0,%1,%2,%3};"
        : "+f"(c[0]), "+f"(c[1]), "+f"(c[2]), "+f"(c[3])
        : "r"(a[0]), "r"(a[1]), "r"(a[2]), "r"(a[3]), "r"(b0), "r"(b1));
}
static __device__ __forceinline__ uint32_t bfpack(__nv_bfloat16 a, __nv_bfloat16 b) {
    return (uint32_t)__bfloat16_as_ushort(a) | ((uint32_t)__bfloat16_as_ushort(b) << 16);
}

// ---------------------------------------------------------------------------
// Convert X -> A' = [hi | hi | lo]  (bf16, row r = t*256+b, K'=768)
// ---------------------------------------------------------------------------
__global__ __launch_bounds__(256) void k_convert(const float* __restrict__ Xh,
                                                 const float* __restrict__ Xf) {
    size_t i = (size_t)blockIdx.x * 256 + threadIdx.x;
    int e8 = (int)(i & 31);
    size_t rr = i >> 5;                                  // cell*MROWS + r
    int cell = (int)(rr >> 17);
    int r = (int)(rr & (MROWS - 1));
    int t = r >> 8, b = r & 255;
    const float* X = cell ? Xf : Xh;
    const float4* src = reinterpret_cast<const float4*>(X + ((size_t)b * LL + t) * EE + e8 * 8);
    float4 v0 = src[0], v1 = src[1];
    float x[8] = {v0.x, v0.y, v0.z, v0.w, v1.x, v1.y, v1.z, v1.w};
    __nv_bfloat16 hi[8], lo[8];
#pragma unroll
    for (int j = 0; j < 8; j++) {
        hi[j] = __float2bfloat16(x[j]);
        lo[j] = __float2bfloat16(x[j] - __bfloat162float(hi[j]));
    }
    uint4 ph, pl;
    ph.x = bfpack(hi[0], hi[1]); ph.y = bfpack(hi[2], hi[3]);
    ph.z = bfpack(hi[4], hi[5]); ph.w = bfpack(hi[6], hi[7]);
    pl.x = bfpack(lo[0], lo[1]); pl.y = bfpack(lo[2], lo[3]);
    pl.z = bfpack(lo[4], lo[5]); pl.w = bfpack(lo[6], lo[7]);
    __nv_bfloat16* dst = g_ap + rr * KTOT + e8 * 8;
    *reinterpret_cast<uint4*>(dst)       = ph;
    *reinterpret_cast<uint4*>(dst + 256) = ph;
    *reinterpret_cast<uint4*>(dst + 512) = pl;
}

// W' = [hi | lo | hi]
__global__ __launch_bounds__(256) void k_convert_w(const float* __restrict__ Wh,
                                                   const float* __restrict__ Wf) {
    int i = blockIdx.x * 256 + threadIdx.x;
    int e8 = i & 31;
    int nn = i >> 5;                                     // cell*512 + n
    int cell = nn >> 9;
    int n = nn & 511;
    const float* W = cell ? Wf : Wh;
    const float4* src = reinterpret_cast<const float4*>(W + (size_t)n * EE + e8 * 8);
    float4 v0 = src[0], v1 = src[1];
    float x[8] = {v0.x, v0.y, v0.z, v0.w, v1.x, v1.y, v1.z, v1.w};
    __nv_bfloat16 hi[8], lo[8];
#pragma unroll
    for (int j = 0; j < 8; j++) {
        hi[j] = __float2bfloat16(x[j]);
        lo[j] = __float2bfloat16(x[j] - __bfloat162float(hi[j]));
    }
    uint4 ph, pl;
    ph.x = bfpack(hi[0], hi[1]); ph.y = bfpack(hi[2], hi[3]);
    ph.z = bfpack(hi[4], hi[5]); ph.w = bfpack(hi[6], hi[7]);
    pl.x = bfpack(lo[0], lo[1]); pl.y = bfpack(lo[2], lo[3]);
    pl.z = bfpack(lo[4], lo[5]); pl.w = bfpack(lo[6], lo[7]);
    __nv_bfloat16* dst = g_wp + (size_t)nn * KTOT + e8 * 8;
    *reinterpret_cast<uint4*>(dst)       = ph;
    *reinterpret_cast<uint4*>(dst + 256) = pl;   // pairs with A hi
    *reinterpret_cast<uint4*>(dst + 512) = ph;   // pairs with A lo
}

// ---------------------------------------------------------------------------
// Phase 1 GEMM via mma.sync bf16 (unchanged — validated in R4/R5)
// ---------------------------------------------------------------------------
#define ASTRIDE 40

__global__ __launch_bounds__(256, 2) void k_mma_gemm(
    const float* __restrict__ bih_h, const float* __restrict__ bhh_h,
    const float* __restrict__ bih_f, const float* __restrict__ bhh_f)
{
    __shared__ __align__(16) __nv_bfloat16 As[2][128 * ASTRIDE];
    __shared__ __align__(16) __nv_bfloat16 Bs[2][128 * ASTRIDE];
    __shared__ float bias_s[128];

    const int tid  = threadIdx.x;
    const int wid  = tid >> 5;
    const int lane = tid & 31;
    const int n0 = blockIdx.x * 128;
    const int m0 = blockIdx.y * 128;
    const int cell = m0 >> 17;

    if (tid < 128) {
        const float* bi = cell ? bih_f : bih_h;
        const float* bh = cell ? bhh_f : bhh_h;
        bias_s[tid] = bi[n0 + tid] + bh[n0 + tid];
    }

    const __nv_bfloat16* Asrc = g_ap + (size_t)m0 * KTOT;
    const __nv_bfloat16* Bsrc = g_wp + ((size_t)cell * G4 + n0) * KTOT;

    const uint32_t sa = smem_u32(&As[0][0]);
    const uint32_t sb = smem_u32(&Bs[0][0]);
    const uint32_t bufstride = 128 * ASTRIDE * 2;

    const int lrow = tid >> 1;
    const int lu   = (tid & 1) * 2;
    const uint32_t a_dst0 = sa + lrow * (ASTRIDE * 2) + lu * 16;
    const uint32_t b_dst0 = sb + lrow * (ASTRIDE * 2) + lu * 16;
    const __nv_bfloat16* a_src0 = Asrc + (size_t)lrow * KTOT + lu * 8;
    const __nv_bfloat16* b_src0 = Bsrc + (size_t)lrow * KTOT + lu * 8;

#define LOAD_CHUNK(c)                                                      \
    do {                                                                   \
        int _buf = (c) & 1;                                                \
        int _k0 = (c) * 32;                                                \
        cp16(a_dst0 + _buf * bufstride,      a_src0 + _k0);                \
        cp16(a_dst0 + _buf * bufstride + 16, a_src0 + _k0 + 8);            \
        cp16(b_dst0 + _buf * bufstride,      b_src0 + _k0);                \
        cp16(b_dst0 + _buf * bufstride + 16, b_src0 + _k0 + 8);            \
        cp_commit();                                                       \
    } while (0)

    const int warp_m = wid & 3;
    const int warp_n = wid >> 2;

    uint32_t a_addr[2];
#pragma unroll
    for (int im = 0; im < 2; im++) {
        int row = warp_m * 32 + im * 16 + (lane & 15);
        a_addr[im] = sa + row * (ASTRIDE * 2) + (lane >> 4) * 16;
    }
    uint32_t b_addr[4];
#pragma unroll
    for (int ip = 0; ip < 4; ip++) {
        int row = warp_n * 64 + ip * 16 + (lane >> 4) * 8 + (lane & 7);
        b_addr[ip] = sb + row * (ASTRIDE * 2) + ((lane >> 3) & 1) * 16;
    }

    float acc[2][8][4];
#pragma unroll
    for (int im = 0; im < 2; im++)
#pragma unroll
        for (int in = 0; in < 8; in++)
#pragma unroll
            for (int q = 0; q < 4; q++) acc[im][in][q] = 0.0f;

    LOAD_CHUNK(0);

    for (int c = 0; c < NCH; ++c) {
        if (c + 1 < NCH) { LOAD_CHUNK(c + 1); cp_wait<1>(); }
        else             { cp_wait<0>(); }
        __syncthreads();

        const uint32_t boff = (uint32_t)(c & 1) * bufstride;
#pragma unroll
        for (int ks = 0; ks < 2; ks++) {
            const uint32_t kb = boff + ks * 32;
            uint32_t afr[2][4];
            ldx4(afr[0], a_addr[0] + kb);
            ldx4(afr[1], a_addr[1] + kb);
            uint32_t bfr[16];
            ldx4(bfr + 0,  b_addr[0] + kb);
            ldx4(bfr + 4,  b_addr[1] + kb);
            ldx4(bfr + 8,  b_addr[2] + kb);
            ldx4(bfr + 12, b_addr[3] + kb);
#pragma unroll
            for (int im = 0; im < 2; im++)
#pragma unroll
                for (int in = 0; in < 8; in++)
                    mma16816(acc[im][in], afr[im], bfr[in * 2], bfr[in * 2 + 1]);
        }
        __syncthreads();
    }

#pragma unroll
    for (int im = 0; im < 2; im++) {
#pragma unroll
        for (int h = 0; h < 2; h++) {
            int m = m0 + warp_m * 32 + im * 16 + h * 8 + (lane >> 2);
            int r = m & (MROWS - 1);
            int t = r >> 8, b = r & 255;
            float* gp = g_gx + (((size_t)cell * LL + t) * BB + b) * G4 + n0;
#pragma unroll
            for (int in = 0; in < 8; in++) {
                int col = warp_n * 64 + in * 8 + (lane & 3) * 2;
                float2 v;
                v.x = acc[im][in][2 * h + 0] + bias_s[col];
                v.y = acc[im][in][2 * h + 1] + bias_s[col + 1];
                *reinterpret_cast<float2*>(gp + col) = v;
            }
        }
    }
}

// ---------------------------------------------------------------------------
// Phase 2: recurrent LSTM. Cluster of 4 CTAs per chain, 256 threads/CTA,
// 2 CTAs (different clusters) co-resident per SM so barrier/dependency
// stalls of one chain hide under the other's compute.
// Rank owns 32 hidden units (=128 gate rows); thread (row=tid>>1, half=tid&1)
// holds a half gate row (32 f32x2 regs); partner combine via shfl.xor(1).
// Pointwise thread (pb=tid>>5, pj=tid&31) owns one (batch, unit); c in reg;
// h broadcast to 3 peers via mapa stores; one syncthreads + one cluster
// barrier per step.
// ---------------------------------------------------------------------------
#define HPAD 136
static __device__ __forceinline__ int hidx(int j) { return j + ((j >> 6) << 2); }

__global__ __launch_bounds__(256, 2) __cluster_dims__(4, 1, 1)
void k_recurrent(const float* __restrict__ Whh_h,
                 const float* __restrict__ Whh_f)
{
    __shared__ float h_s[2][TB][HPAD];      // 8.7 KB double-buffered hidden
    __shared__ float gates_s[128][TB + 1];  // 4.6 KB h.W partials (local rows)

    const int tid = threadIdx.x;
    uint32_t rank;
    asm("mov.u32 %0, %%cluster_ctarank;" : "=r"(rank));
    const int q    = blockIdx.x >> 2;       // cluster id
    const int cell = q >> 5;
    const int b0   = (q & 31) * TB;

    const float* W = cell ? Whh_f : Whh_h;

    // matvec mapping: 128 local gate rows x 2 halves
    const int row  = tid >> 1;              // 0..127
    const int half = tid & 1;
    const int g    = row >> 5;              // gate 0..3
    const int ju   = row & 31;              // unit within rank slice
    const int n    = g * HH + (int)rank * 32 + ju;   // global gate row

    unsigned long long w2[32];              // half gate row (64 floats)
    {
        const float2* wrow = reinterpret_cast<const float2*>(W + (size_t)n * HH + half * 64);
#pragma unroll
        for (int i = 0; i < 32; i++) {
            float2 v = wrow[i];
            w2[i] = pack2(v.x, v.y);
        }
    }

    // pointwise mapping
    const int pb = tid >> 5;                // 0..7
    const int pj = tid & 31;                // 0..31
    const int jglob = (int)rank * 32 + pj;
    const uint32_t h_local0 = smem_u32(&h_s[0][pb][hidx(jglob)]);
    const uint32_t h_local1 = smem_u32(&h_s[1][pb][hidx(jglob)]);
    float* hg = g_h + (((size_t)cell * BB + b0 + pb) * LL) * HH + jglob;

    for (int i = tid; i < 2 * TB * HPAD; i += 256) (&h_s[0][0][0])[i] = 0.0f;
    float c_reg = 0.0f;
    __syncthreads();
    asm volatile("barrier.cluster.arrive.aligned;" ::: "memory");
    asm volatile("barrier.cluster.wait.aligned;"   ::: "memory");

    // Gx: 4 gate values for (pj), batch pb:  gxbase + g*128 + t*BB*G4
    const float* gxbase = g_gx + ((size_t)cell * LL * BB + (b0 + pb)) * G4 + jglob;
    float gxr[4];
#pragma unroll
    for (int gi = 0; gi < 4; gi++)
        gxr[gi] = gxbase[gi * HH];          // t = 0

    int buf = 0;
    for (int t = 0; t < LL; t++) {
        // ---- matvec: gates_s[row][b] = h[b] . w_half (halves combined via shfl)
#pragma unroll
        for (int bp = 0; bp < TB; bp += 2) {
            const longlong2* hp0 =
                reinterpret_cast<const longlong2*>(&h_s[buf][bp][half * 68]);
            const longlong2* hp1 =
                reinterpret_cast<const longlong2*>(&h_s[buf][bp + 1][half * 68]);
            unsigned long long a00 = 0ull, a01 = 0ull, a10 = 0ull, a11 = 0ull;
#pragma unroll
            for (int i = 0; i < 16; i++) {
                longlong2 v0 = hp0[i];
                longlong2 v1 = hp1[i];
                fma2(a00, (unsigned long long)v0.x, w2[2 * i]);
                fma2(a01, (unsigned long long)v0.y, w2[2 * i + 1]);
                fma2(a10, (unsigned long long)v1.x, w2[2 * i]);
                fma2(a11, (unsigned long long)v1.y, w2[2 * i + 1]);
            }
            float2 s00 = unpack2(a00), s01 = unpack2(a01);
            float2 s10 = unpack2(a10), s11 = unpack2(a11);
            float p0 = (s00.x + s00.y) + (s01.x + s01.y);
            float p1 = (s10.x + s10.y) + (s11.x + s11.y);
            float t0 = p0 + __shfl_xor_sync(0xffffffffu, p0, 1);
            float t1 = p1 + __shfl_xor_sync(0xffffffffu, p1, 1);
            if (!half) {
                gates_s[row][bp]     = t0;
                gates_s[row][bp + 1] = t1;
            }
        }
        __syncthreads();

        // ---- pointwise: unit (pb, jglob)
        float gi_ = gates_s[pj][pb]        + gxr[0];
        float gf_ = gates_s[32 + pj][pb]   + gxr[1];
        float gg_ = gates_s[64 + pj][pb]   + gxr[2];
        float go_ = gates_s[96 + pj][pb]   + gxr[3];
        float ig = sigm(gi_);
        float fg = sigm(gf_);
        float gv = tanha(gg_);
        float og = sigm(go_);
        c_reg = fg * c_reg + ig * gv;
        float hv = og * tanha(c_reg);

        const int nb = buf ^ 1;
        h_s[nb][pb][hidx(jglob)] = hv;
        const uint32_t hla = nb ? h_local1 : h_local0;
#pragma unroll
        for (int r = 1; r < 4; r++)
            st_remote_f32(hla, (rank + r) & 3u, hv);
        hg[(size_t)t * HH] = hv;

        // prefetch Gx for t+1 (hidden under next step's matvec)
        if (t + 1 < LL) {
            const float* gp = gxbase + (size_t)(t + 1) * BB * G4;
#pragma unroll
            for (int gi2 = 0; gi2 < 4; gi2++)
                gxr[gi2] = gp[gi2 * HH];
        }

        asm volatile("barrier.cluster.arrive.aligned;" ::: "memory");
        asm volatile("barrier.cluster.wait.aligned;"   ::: "memory");
        buf = nb;
    }
}

// ---------------------------------------------------------------------------
// Phase 3: y[b][t] = W_ffn . [h_h(b,t); h_f(b,t)] + b_ffn
// ---------------------------------------------------------------------------
__global__ __launch_bounds__(256) void k_finalize(float* __restrict__ out,
                                                  const float* __restrict__ Wffn,
                                                  const float* __restrict__ bffn) {
    __shared__ float wf[2 * HH];
    const int b = blockIdx.x;
    const int tid = threadIdx.x;
    wf[tid] = Wffn[tid];
    __syncthreads();
    const float bias = bffn[0];

    for (int t = tid; t < LL; t += 256) {
        const float4* p0 = reinterpret_cast<const float4*>(
            g_h + (((size_t)0 * BB + b) * LL + t) * HH);
        const float4* p1 = reinterpret_cast<const float4*>(
            g_h + (((size_t)1 * BB + b) * LL + t) * HH);
        float acc = bias;
#pragma unroll 8
        for (int q = 0; q < 32; q++) {
            float4 a = p0[q];
            acc += a.x * wf[4 * q] + a.y * wf[4 * q + 1]
                 + a.z * wf[4 * q + 2] + a.w * wf[4 * q + 3];
        }
#pragma unroll 8
        for (int q = 0; q < 32; q++) {
            float4 a = p1[q];
            acc += a.x * wf[128 + 4 * q] + a.y * wf[128 + 4 * q + 1]
                 + a.z * wf[128 + 4 * q + 2] + a.w * wf[128 + 4 * q + 3];
        }
        out[(size_t)b * LL + t] = acc;
    }
}

// ---------------------------------------------------------------------------
extern "C" void kernel_launch(void* const* d_in, const int* in_sizes, int n_in,
                              void* d_out, int out_size) {
    const float* hist  = (const float*)d_in[0];
    const float* fut   = (const float*)d_in[1];
    const float* Wih_h = (const float*)d_in[2];
    const float* Whh_h = (const float*)d_in[3];
    const float* bih_h = (const float*)d_in[4];
    const float* bhh_h = (const float*)d_in[5];
    const float* Wih_f = (const float*)d_in[6];
    const float* Whh_f = (const float*)d_in[7];
    const float* bih_f = (const float*)d_in[8];
    const float* bhh_f = (const float*)d_in[9];
    const float* Wffn  = (const float*)d_in[10];
    const float* bffn  = (const float*)d_in[11];
    float* out = (float*)d_out;

    k_convert<<<(2 * MROWS * 32) / 256, 256>>>(hist, fut);
    k_convert_w<<<(2 * G4 * 32) / 256, 256>>>(Wih_h, Wih_f);

    dim3 gg(G4 / 128, (2 * MROWS) / 128);   // (4, 2048)
    k_mma_gemm<<<gg, 256>>>(bih_h, bhh_h, bih_f, bhh_f);

    k_recurrent<<<256, 256>>>(Whh_h, Whh_f);

    k_finalize<<<BB, 256>>>(out, Wffn, bffn);
}